// round 16
// baseline (speedup 1.0000x reference)
#include <cuda_runtime.h>
#include <cuda_bf16.h>
#include <cstdint>

// ============================================================
// W8A8 linear: out[M,N] = xs * (Xq[M,K] @ Wq[N,K]^T) * wsc[n] + bias[n]
//   M = 8192, N = 4096, K = 4096
// Base-sm_103 (compute_103 virtual arch; no tcgen05).
// Round 16: revert to R14 (best, 638.9us) — the fused single-kernel
// experiment had an unfixable-risk cross-CTA sync flaw. One safe
// change: quantize pass widened to 32 floats/thread (MLP=8) to close
// the remaining gap to its ~36us DRAM floor.
//   - GEMM: 2 CTAs/SM, BK=64, 3-stage ring, dynamic tiles, global-
//     read epilogue (unchanged from R14).
//   - Counter reset folded into the quantize kernel.
// ============================================================

#define MM 8192
#define NN 4096
#define KK 4096

#define BM 128
#define BN 128
#define BK 64                 // bf16 elements; 128 bytes per row
#define STAGES 3
#define KITERS (KK / BK)      // 64
#define NTHREADS 128          // 4 warps
#define TILES_X (NN / BN)     // 32
#define NTILES ((MM / BM) * (NN / BN))   // 2048

// ---- device scratch: quantized bf16 operands + tile counter ----
__device__ __align__(128) __nv_bfloat16 g_xq[(size_t)MM * KK];
__device__ __align__(128) __nv_bfloat16 g_wq[(size_t)NN * KK];
__device__ int g_ctr;

// ============================================================
// PTX helpers (base-arch only)
// ============================================================
__device__ __forceinline__ uint32_t smem_to_u32(const void* p) {
    uint32_t a;
    asm("{ .reg .u64 t; cvta.to.shared.u64 t, %1; cvt.u32.u64 %0, t; }"
        : "=r"(a) : "l"(p));
    return a;
}

__device__ __forceinline__ void cp_async16(uint32_t dst, const void* src) {
    asm volatile("cp.async.cg.shared.global [%0], [%1], 16;"
                 :: "r"(dst), "l"(src) : "memory");
}
#define CP_COMMIT() asm volatile("cp.async.commit_group;" ::: "memory")
#define CP_WAIT(n)  asm volatile("cp.async.wait_group %0;" :: "n"(n) : "memory")

#define LDMATRIX_X4(r, addr) \
    asm volatile("ldmatrix.sync.aligned.m8n8.x4.shared.b16 {%0,%1,%2,%3}, [%4];" \
                 : "=r"((r)[0]), "=r"((r)[1]), "=r"((r)[2]), "=r"((r)[3]) \
                 : "r"(addr))

// D(16x8 f32) += A(16x16 bf16, row-major) * B(16x8 bf16, col operand)
__device__ __forceinline__ void mma_bf16(float* d, const uint32_t* a,
                                         uint32_t b0, uint32_t b1) {
    asm volatile(
        "mma.sync.aligned.m16n8k16.row.col.f32.bf16.bf16.f32 "
        "{%0,%1,%2,%3}, {%4,%5,%6,%7}, {%8,%9}, {%0,%1,%2,%3};"
        : "+f"(d[0]), "+f"(d[1]), "+f"(d[2]), "+f"(d[3])
        : "r"(a[0]), "r"(a[1]), "r"(a[2]), "r"(a[3]),
          "r"(b0), "r"(b1));
}

// ============================================================
// Quantization pre-pass: 32 floats per thread (8 independent
// float4 loads -> MLP=8), 4x uint4 stores. Also resets g_ctr.
// ============================================================
__device__ __forceinline__ uint2 quant4_bf16(float4 v, float inv) {
    float a = fminf(127.f, fmaxf(-128.f, rintf(v.x * inv)));
    float b = fminf(127.f, fmaxf(-128.f, rintf(v.y * inv)));
    float c = fminf(127.f, fmaxf(-128.f, rintf(v.z * inv)));
    float d = fminf(127.f, fmaxf(-128.f, rintf(v.w * inv)));
    __nv_bfloat162 lo = __floats2bfloat162_rn(a, b);
    __nv_bfloat162 hi = __floats2bfloat162_rn(c, d);
    uint2 p;
    p.x = *reinterpret_cast<uint32_t*>(&lo);
    p.y = *reinterpret_cast<uint32_t*>(&hi);
    return p;
}

__device__ __forceinline__ uint2 pass4_bf16(float4 v) {
    __nv_bfloat162 lo = __floats2bfloat162_rn(v.x, v.y);
    __nv_bfloat162 hi = __floats2bfloat162_rn(v.z, v.w);
    uint2 p;
    p.x = *reinterpret_cast<uint32_t*>(&lo);
    p.y = *reinterpret_cast<uint32_t*>(&hi);
    return p;
}

__global__ void quantize_kernel(const float4* __restrict__ x4,
                                const float4* __restrict__ w4,
                                const float* __restrict__ xs_ptr,
                                int nthx, int nthtot, int ctr_start) {
    int t = blockIdx.x * blockDim.x + threadIdx.x;
    if (t == 0) g_ctr = ctr_start;          // folded counter reset
    if (t >= nthtot) return;

    if (t < nthx) {
        float inv = 1.0f / __ldg(xs_ptr);
        const float4* src = x4 + (size_t)t * 8;
        float4 v[8];
        #pragma unroll
        for (int i = 0; i < 8; i++) v[i] = __ldg(src + i);   // MLP = 8
        uint4* dst = reinterpret_cast<uint4*>(g_xq) + (size_t)t * 4;
        #pragma unroll
        for (int i = 0; i < 4; i++) {
            uint2 pa = quant4_bf16(v[2 * i],     inv);
            uint2 pb = quant4_bf16(v[2 * i + 1], inv);
            dst[i] = make_uint4(pa.x, pa.y, pb.x, pb.y);
        }
    } else {
        int j = t - nthx;
        const float4* src = w4 + (size_t)j * 8;
        float4 v[8];
        #pragma unroll
        for (int i = 0; i < 8; i++) v[i] = __ldg(src + i);   // MLP = 8
        uint4* dst = reinterpret_cast<uint4*>(g_wq) + (size_t)j * 4;
        #pragma unroll
        for (int i = 0; i < 4; i++) {
            uint2 pa = pass4_bf16(v[2 * i]);
            uint2 pb = pass4_bf16(v[2 * i + 1]);
            dst[i] = make_uint4(pa.x, pa.y, pb.x, pb.y);
        }
    }
}

// ============================================================
// GEMM kernel: 2 CTAs/SM, persistent, 3-stage ring, BK=64.
//   128 threads = 4 warps, warp grid 2(m) x 2(n), warp tile 64x64.
//   Rows are 128B; 16B-chunk XOR swizzle (validated rounds 3-14).
// Dynamic tiles: first tile = blockIdx.x; thereafter from g_ctr,
// prefetched one tile ahead through smem (published at kit-0 barrier).
// Epilogue reads wsc/bias straight from global (L2-hot).
// ============================================================
#define SOFF_NEXT 0
#define SOFF_ST   1024
#define ROWB      128
#define STAGE_BYTES ((BM + BN) * ROWB)         // 32768
#define ASTAGE(s) (SOFF_ST + (s) * STAGE_BYTES)
#define BSTAGE(s) (ASTAGE(s) + BM * ROWB)
#define SMEM_TOTAL (SOFF_ST + STAGES * STAGE_BYTES)   // 99328

__device__ __forceinline__ uint32_t swz(int row, int chunk) {
    return (uint32_t)(row * ROWB + ((chunk ^ (row & 7)) << 4));
}

__device__ __forceinline__ void load_stage(uint32_t sb, int s, int kiter,
                                           int m0, int n0, int tid) {
    int k0 = kiter * BK;
    const __nv_bfloat16* Ab = g_xq + (size_t)m0 * KK + k0;
    const __nv_bfloat16* Bb = g_wq + (size_t)n0 * KK + k0;
    #pragma unroll
    for (int i = 0; i < (BM + BN) * 8 / NTHREADS; i++) {   // 16
        int idx = tid + i * NTHREADS;
        int row = idx >> 3;
        int c = idx & 7;
        if (row < BM) {
            cp_async16(sb + ASTAGE(s) + swz(row, c),
                       Ab + (size_t)row * KK + c * 8);
        } else {
            int br = row - BM;
            cp_async16(sb + BSTAGE(s) + swz(br, c),
                       Bb + (size_t)br * KK + c * 8);
        }
    }
}

__global__ void __launch_bounds__(NTHREADS, 2)
w8a8_gemm_kernel(float* __restrict__ out,
                 const float* __restrict__ wsc,
                 const float* __restrict__ bias,
                 const float* __restrict__ xs_ptr) {
    extern __shared__ char smem[];
    uint32_t sb = smem_to_u32(smem);
    int tid  = threadIdx.x;
    int wid  = tid >> 5;
    int lane = tid & 31;
    int warp_m = wid & 1;     // m offset warp_m*64
    int warp_n = wid >> 1;    // n offset warp_n*64

    volatile int* s_next = reinterpret_cast<volatile int*>(smem + SOFF_NEXT);

    int cur = blockIdx.x;     // first tile: static (counter starts at grid)

    // ---- load cursor: starts on tile cur, kit 0 ----
    int ltile = cur;
    int lkit  = 0;
    int ls    = 0;

    // prologue: fill 2 of 3 stages (both kits belong to tile cur; KITERS>2)
    #pragma unroll
    for (int p = 0; p < STAGES - 1; p++) {
        load_stage(sb, ls, lkit, (ltile / TILES_X) * BM,
                   (ltile % TILES_X) * BN, tid);
        if (++ls == STAGES) ls = 0;
        ++lkit;
        CP_COMMIT();
    }

    float xs = __ldg(xs_ptr);

    // ldmatrix lane address components (validated rounds 3-14)
    int arow  = lane & 15;                        // A rows within m16
    int ahalf = lane >> 4;                        // A 16B half of k16 (32B)
    int brow  = (lane & 7) + ((lane & 16) >> 1);  // B n-rows (two n8 tiles)
    int bhalf = (lane >> 3) & 1;                  // B 16B half of k16

    int cs = 0;   // compute stage (FIFO with loads, carried across tiles)

    for (;;) {
        int m0 = (cur / TILES_X) * BM;
        int n0 = (cur % TILES_X) * BN;

        // fetch next tile id one tile ahead (published by kit-0 barrier)
        if (tid == 0) *s_next = atomicAdd(&g_ctr, 1);

        float acc[4][8][4] = {};   // [m16 tile][n8 tile][frag]

        for (int kit = 0; kit < KITERS; kit++) {
            CP_WAIT(1);           // this kit's group done (one newer allowed)
            __syncthreads();      // visibility + stage-reuse + s_next publish

            // issue loads for kit+2 into ring stage ls
            if (ltile < NTILES) {
                load_stage(sb, ls, lkit, (ltile / TILES_X) * BM,
                           (ltile % TILES_X) * BN, tid);
                if (++ls == STAGES) ls = 0;
                if (++lkit == KITERS) {
                    lkit = 0;
                    ltile = *s_next;   // cross into the next dynamic tile
                }
            }
            CP_COMMIT();          // unconditional: keeps wait(1) invariant

            uint32_t As = sb + ASTAGE(cs);
            uint32_t Bs = sb + BSTAGE(cs);
            if (++cs == STAGES) cs = 0;

            #pragma unroll
            for (int j = 0; j < BK / 16; j++) {      // 4 k16 steps
                uint32_t a[4][4];
                #pragma unroll
                for (int t = 0; t < 4; t++) {
                    int row = warp_m * 64 + t * 16 + arow;
                    LDMATRIX_X4(a[t], As + swz(row, j * 2 + ahalf));
                }
                uint32_t b[4][4];
                #pragma unroll
                for (int p = 0; p < 4; p++) {
                    int row = warp_n * 64 + p * 16 + brow;
                    LDMATRIX_X4(b[p], Bs + swz(row, j * 2 + bhalf));
                }
                #pragma unroll
                for (int t = 0; t < 4; t++) {
                    #pragma unroll
                    for (int p = 0; p < 4; p++) {
                        mma_bf16(acc[t][2 * p],     a[t], b[p][0], b[p][1]);
                        mma_bf16(acc[t][2 * p + 1], a[t], b[p][2], b[p][3]);
                    }
                }
            }
        }

        // -------- epilogue: out = acc * xs * wsc[n] + bias[n] --------
        // wsc/bias read straight from global (32KB each, L2-hot).
        int rbase = m0 + warp_m * 64 + (lane >> 2);
        #pragma unroll
        for (int q = 0; q < 8; q++) {
            int col = warp_n * 64 + q * 8 + (lane & 3) * 2;
            float2 scv = __ldg(reinterpret_cast<const float2*>(wsc + n0 + col));
            float2 biv = __ldg(reinterpret_cast<const float2*>(bias + n0 + col));
            float s0 = xs * scv.x, s1 = xs * scv.y;
            #pragma unroll
            for (int t = 0; t < 4; t++) {
                int row = rbase + t * 16;
                float2 v0, v1;
                v0.x = acc[t][q][0] * s0 + biv.x;
                v0.y = acc[t][q][1] * s1 + biv.y;
                v1.x = acc[t][q][2] * s0 + biv.x;
                v1.y = acc[t][q][3] * s1 + biv.y;
                *reinterpret_cast<float2*>(out + (size_t)row * NN + n0 + col) = v0;
                *reinterpret_cast<float2*>(out + (size_t)(row + 8) * NN + n0 + col) = v1;
            }
        }

        __syncthreads();          // all threads past s_next's current value
        int nt = *s_next;
        if (nt >= NTILES) break;
        cur = nt;
    }
}

// ============================================================
// kernel_launch
// Inputs: x[8192*4096] f32, weight_int8[4096*4096] f32,
//         w_scale[4096] f32, bias[4096] f32, x_scale[1] f32
// Output: f32 [8192*4096]
// ============================================================
extern "C" void kernel_launch(void* const* d_in, const int* in_sizes, int n_in,
                              void* d_out, int out_size) {
    const float* x    = (const float*)d_in[0];
    const float* w    = (const float*)d_in[1];
    const float* wsc  = (const float*)d_in[2];
    const float* bias = (const float*)d_in[3];
    const float* xs   = (const float*)d_in[4];
    float* out = (float*)d_out;

    static int n_sm = 0;
    if (n_sm == 0) {
        cudaDeviceGetAttribute(&n_sm, cudaDevAttrMultiProcessorCount, 0);
        if (n_sm <= 0) n_sm = 148;
        cudaFuncSetAttribute(w8a8_gemm_kernel,
                             cudaFuncAttributeMaxDynamicSharedMemorySize,
                             SMEM_TOTAL);
    }

    int grid = 2 * n_sm;
    if (grid > NTILES) grid = NTILES;

    // quantize pre-pass (32 floats/thread, MLP=8; also resets g_ctr)
    int nthx = MM * KK / 32;
    int nthw = NN * KK / 32;
    int nthtot = nthx + nthw;
    quantize_kernel<<<(nthtot + 255) / 256, 256>>>(
        (const float4*)x, (const float4*)w, xs, nthx, nthtot, grid);

    // persistent GEMM, 2 CTAs per SM, dynamic tiles
    w8a8_gemm_kernel<<<grid, NTHREADS, SMEM_TOTAL>>>(out, wsc, bias, xs);
}

// round 17
// speedup vs baseline: 1.0163x; 1.0163x over previous
#include <cuda_runtime.h>
#include <cuda_bf16.h>
#include <cstdint>

// ============================================================
// W8A8 linear: out[M,N] = xs * (Xq[M,K] @ Wq[N,K]^T) * wsc[n] + bias[n]
//   M = 8192, N = 4096, K = 4096
// Base-sm_103 (compute_103 virtual arch; no tcgen05).
// Round 17: exact restore of the best-measured build (R14, 638.9us).
//   - GEMM: 2 CTAs/SM, BK=64, 3-stage cp.async ring, dynamic tiles
//     via global atomic counter, global-read epilogue.
//     (At the fallback-HMMA plateau ~0.39 HMMA/cyc/SM and the
//      work/worker scheduling bound — 5 variants confirmed.)
//   - Quantize: 16 floats/thread, MLP=4 (~41us = 88% of HBM spec;
//     MLP=8 regressed and is reverted).
//   - Counter reset folded into the quantize kernel.
// ============================================================

#define MM 8192
#define NN 4096
#define KK 4096

#define BM 128
#define BN 128
#define BK 64                 // bf16 elements; 128 bytes per row
#define STAGES 3
#define KITERS (KK / BK)      // 64
#define NTHREADS 128          // 4 warps
#define TILES_X (NN / BN)     // 32
#define NTILES ((MM / BM) * (NN / BN))   // 2048

// ---- device scratch: quantized bf16 operands + tile counter ----
__device__ __align__(128) __nv_bfloat16 g_xq[(size_t)MM * KK];
__device__ __align__(128) __nv_bfloat16 g_wq[(size_t)NN * KK];
__device__ int g_ctr;

// ============================================================
// PTX helpers (base-arch only)
// ============================================================
__device__ __forceinline__ uint32_t smem_to_u32(const void* p) {
    uint32_t a;
    asm("{ .reg .u64 t; cvta.to.shared.u64 t, %1; cvt.u32.u64 %0, t; }"
        : "=r"(a) : "l"(p));
    return a;
}

__device__ __forceinline__ void cp_async16(uint32_t dst, const void* src) {
    asm volatile("cp.async.cg.shared.global [%0], [%1], 16;"
                 :: "r"(dst), "l"(src) : "memory");
}
#define CP_COMMIT() asm volatile("cp.async.commit_group;" ::: "memory")
#define CP_WAIT(n)  asm volatile("cp.async.wait_group %0;" :: "n"(n) : "memory")

#define LDMATRIX_X4(r, addr) \
    asm volatile("ldmatrix.sync.aligned.m8n8.x4.shared.b16 {%0,%1,%2,%3}, [%4];" \
                 : "=r"((r)[0]), "=r"((r)[1]), "=r"((r)[2]), "=r"((r)[3]) \
                 : "r"(addr))

// D(16x8 f32) += A(16x16 bf16, row-major) * B(16x8 bf16, col operand)
__device__ __forceinline__ void mma_bf16(float* d, const uint32_t* a,
                                         uint32_t b0, uint32_t b1) {
    asm volatile(
        "mma.sync.aligned.m16n8k16.row.col.f32.bf16.bf16.f32 "
        "{%0,%1,%2,%3}, {%4,%5,%6,%7}, {%8,%9}, {%0,%1,%2,%3};"
        : "+f"(d[0]), "+f"(d[1]), "+f"(d[2]), "+f"(d[3])
        : "r"(a[0]), "r"(a[1]), "r"(a[2]), "r"(a[3]),
          "r"(b0), "r"(b1));
}

// ============================================================
// Quantization pre-pass: 16 floats per thread (4 independent
// float4 loads -> MLP=4), 32B uint4 stores. Also resets g_ctr.
// ============================================================
__device__ __forceinline__ uint2 quant4_bf16(float4 v, float inv) {
    float a = fminf(127.f, fmaxf(-128.f, rintf(v.x * inv)));
    float b = fminf(127.f, fmaxf(-128.f, rintf(v.y * inv)));
    float c = fminf(127.f, fmaxf(-128.f, rintf(v.z * inv)));
    float d = fminf(127.f, fmaxf(-128.f, rintf(v.w * inv)));
    __nv_bfloat162 lo = __floats2bfloat162_rn(a, b);
    __nv_bfloat162 hi = __floats2bfloat162_rn(c, d);
    uint2 p;
    p.x = *reinterpret_cast<uint32_t*>(&lo);
    p.y = *reinterpret_cast<uint32_t*>(&hi);
    return p;
}

__device__ __forceinline__ uint2 pass4_bf16(float4 v) {
    __nv_bfloat162 lo = __floats2bfloat162_rn(v.x, v.y);
    __nv_bfloat162 hi = __floats2bfloat162_rn(v.z, v.w);
    uint2 p;
    p.x = *reinterpret_cast<uint32_t*>(&lo);
    p.y = *reinterpret_cast<uint32_t*>(&hi);
    return p;
}

__global__ void quantize_kernel(const float4* __restrict__ x4,
                                const float4* __restrict__ w4,
                                const float* __restrict__ xs_ptr,
                                int nthx, int nthtot, int ctr_start) {
    int t = blockIdx.x * blockDim.x + threadIdx.x;
    if (t == 0) g_ctr = ctr_start;          // folded counter reset
    if (t >= nthtot) return;

    if (t < nthx) {
        float inv = 1.0f / __ldg(xs_ptr);
        const float4* src = x4 + (size_t)t * 4;
        float4 v0 = src[0], v1 = src[1], v2 = src[2], v3 = src[3];
        uint2 p0 = quant4_bf16(v0, inv), p1 = quant4_bf16(v1, inv);
        uint2 p2 = quant4_bf16(v2, inv), p3 = quant4_bf16(v3, inv);
        uint4* dst = reinterpret_cast<uint4*>(g_xq) + (size_t)t * 2;
        dst[0] = make_uint4(p0.x, p0.y, p1.x, p1.y);
        dst[1] = make_uint4(p2.x, p2.y, p3.x, p3.y);
    } else {
        int j = t - nthx;
        const float4* src = w4 + (size_t)j * 4;
        float4 v0 = src[0], v1 = src[1], v2 = src[2], v3 = src[3];
        uint2 p0 = pass4_bf16(v0), p1 = pass4_bf16(v1);
        uint2 p2 = pass4_bf16(v2), p3 = pass4_bf16(v3);
        uint4* dst = reinterpret_cast<uint4*>(g_wq) + (size_t)j * 2;
        dst[0] = make_uint4(p0.x, p0.y, p1.x, p1.y);
        dst[1] = make_uint4(p2.x, p2.y, p3.x, p3.y);
    }
}

// ============================================================
// GEMM kernel: 2 CTAs/SM, persistent, 3-stage ring, BK=64.
//   128 threads = 4 warps, warp grid 2(m) x 2(n), warp tile 64x64.
//   Rows are 128B; 16B-chunk XOR swizzle (validated rounds 3-16).
// Dynamic tiles: first tile = blockIdx.x; thereafter from g_ctr,
// prefetched one tile ahead through smem (published at kit-0 barrier).
// Epilogue reads wsc/bias straight from global (L2-hot).
// ============================================================
#define SOFF_NEXT 0
#define SOFF_ST   1024
#define ROWB      128
#define STAGE_BYTES ((BM + BN) * ROWB)         // 32768
#define ASTAGE(s) (SOFF_ST + (s) * STAGE_BYTES)
#define BSTAGE(s) (ASTAGE(s) + BM * ROWB)
#define SMEM_TOTAL (SOFF_ST + STAGES * STAGE_BYTES)   // 99328

__device__ __forceinline__ uint32_t swz(int row, int chunk) {
    return (uint32_t)(row * ROWB + ((chunk ^ (row & 7)) << 4));
}

__device__ __forceinline__ void load_stage(uint32_t sb, int s, int kiter,
                                           int m0, int n0, int tid) {
    int k0 = kiter * BK;
    const __nv_bfloat16* Ab = g_xq + (size_t)m0 * KK + k0;
    const __nv_bfloat16* Bb = g_wq + (size_t)n0 * KK + k0;
    #pragma unroll
    for (int i = 0; i < (BM + BN) * 8 / NTHREADS; i++) {   // 16
        int idx = tid + i * NTHREADS;
        int row = idx >> 3;
        int c = idx & 7;
        if (row < BM) {
            cp_async16(sb + ASTAGE(s) + swz(row, c),
                       Ab + (size_t)row * KK + c * 8);
        } else {
            int br = row - BM;
            cp_async16(sb + BSTAGE(s) + swz(br, c),
                       Bb + (size_t)br * KK + c * 8);
        }
    }
}

__global__ void __launch_bounds__(NTHREADS, 2)
w8a8_gemm_kernel(float* __restrict__ out,
                 const float* __restrict__ wsc,
                 const float* __restrict__ bias,
                 const float* __restrict__ xs_ptr) {
    extern __shared__ char smem[];
    uint32_t sb = smem_to_u32(smem);
    int tid  = threadIdx.x;
    int wid  = tid >> 5;
    int lane = tid & 31;
    int warp_m = wid & 1;     // m offset warp_m*64
    int warp_n = wid >> 1;    // n offset warp_n*64

    volatile int* s_next = reinterpret_cast<volatile int*>(smem + SOFF_NEXT);

    int cur = blockIdx.x;     // first tile: static (counter starts at grid)

    // ---- load cursor: starts on tile cur, kit 0 ----
    int ltile = cur;
    int lkit  = 0;
    int ls    = 0;

    // prologue: fill 2 of 3 stages (both kits belong to tile cur; KITERS>2)
    #pragma unroll
    for (int p = 0; p < STAGES - 1; p++) {
        load_stage(sb, ls, lkit, (ltile / TILES_X) * BM,
                   (ltile % TILES_X) * BN, tid);
        if (++ls == STAGES) ls = 0;
        ++lkit;
        CP_COMMIT();
    }

    float xs = __ldg(xs_ptr);

    // ldmatrix lane address components (validated rounds 3-16)
    int arow  = lane & 15;                        // A rows within m16
    int ahalf = lane >> 4;                        // A 16B half of k16 (32B)
    int brow  = (lane & 7) + ((lane & 16) >> 1);  // B n-rows (two n8 tiles)
    int bhalf = (lane >> 3) & 1;                  // B 16B half of k16

    int cs = 0;   // compute stage (FIFO with loads, carried across tiles)

    for (;;) {
        int m0 = (cur / TILES_X) * BM;
        int n0 = (cur % TILES_X) * BN;

        // fetch next tile id one tile ahead (published by kit-0 barrier)
        if (tid == 0) *s_next = atomicAdd(&g_ctr, 1);

        float acc[4][8][4] = {};   // [m16 tile][n8 tile][frag]

        for (int kit = 0; kit < KITERS; kit++) {
            CP_WAIT(1);           // this kit's group done (one newer allowed)
            __syncthreads();      // visibility + stage-reuse + s_next publish

            // issue loads for kit+2 into ring stage ls
            if (ltile < NTILES) {
                load_stage(sb, ls, lkit, (ltile / TILES_X) * BM,
                           (ltile % TILES_X) * BN, tid);
                if (++ls == STAGES) ls = 0;
                if (++lkit == KITERS) {
                    lkit = 0;
                    ltile = *s_next;   // cross into the next dynamic tile
                }
            }
            CP_COMMIT();          // unconditional: keeps wait(1) invariant

            uint32_t As = sb + ASTAGE(cs);
            uint32_t Bs = sb + BSTAGE(cs);
            if (++cs == STAGES) cs = 0;

            #pragma unroll
            for (int j = 0; j < BK / 16; j++) {      // 4 k16 steps
                uint32_t a[4][4];
                #pragma unroll
                for (int t = 0; t < 4; t++) {
                    int row = warp_m * 64 + t * 16 + arow;
                    LDMATRIX_X4(a[t], As + swz(row, j * 2 + ahalf));
                }
                uint32_t b[4][4];
                #pragma unroll
                for (int p = 0; p < 4; p++) {
                    int row = warp_n * 64 + p * 16 + brow;
                    LDMATRIX_X4(b[p], Bs + swz(row, j * 2 + bhalf));
                }
                #pragma unroll
                for (int t = 0; t < 4; t++) {
                    #pragma unroll
                    for (int p = 0; p < 4; p++) {
                        mma_bf16(acc[t][2 * p],     a[t], b[p][0], b[p][1]);
                        mma_bf16(acc[t][2 * p + 1], a[t], b[p][2], b[p][3]);
                    }
                }
            }
        }

        // -------- epilogue: out = acc * xs * wsc[n] + bias[n] --------
        // wsc/bias read straight from global (32KB each, L2-hot).
        int rbase = m0 + warp_m * 64 + (lane >> 2);
        #pragma unroll
        for (int q = 0; q < 8; q++) {
            int col = warp_n * 64 + q * 8 + (lane & 3) * 2;
            float2 scv = __ldg(reinterpret_cast<const float2*>(wsc + n0 + col));
            float2 biv = __ldg(reinterpret_cast<const float2*>(bias + n0 + col));
            float s0 = xs * scv.x, s1 = xs * scv.y;
            #pragma unroll
            for (int t = 0; t < 4; t++) {
                int row = rbase + t * 16;
                float2 v0, v1;
                v0.x = acc[t][q][0] * s0 + biv.x;
                v0.y = acc[t][q][1] * s1 + biv.y;
                v1.x = acc[t][q][2] * s0 + biv.x;
                v1.y = acc[t][q][3] * s1 + biv.y;
                *reinterpret_cast<float2*>(out + (size_t)row * NN + n0 + col) = v0;
                *reinterpret_cast<float2*>(out + (size_t)(row + 8) * NN + n0 + col) = v1;
            }
        }

        __syncthreads();          // all threads past s_next's current value
        int nt = *s_next;
        if (nt >= NTILES) break;
        cur = nt;
    }
}

// ============================================================
// kernel_launch
// Inputs: x[8192*4096] f32, weight_int8[4096*4096] f32,
//         w_scale[4096] f32, bias[4096] f32, x_scale[1] f32
// Output: f32 [8192*4096]
// ============================================================
extern "C" void kernel_launch(void* const* d_in, const int* in_sizes, int n_in,
                              void* d_out, int out_size) {
    const float* x    = (const float*)d_in[0];
    const float* w    = (const float*)d_in[1];
    const float* wsc  = (const float*)d_in[2];
    const float* bias = (const float*)d_in[3];
    const float* xs   = (const float*)d_in[4];
    float* out = (float*)d_out;

    static int n_sm = 0;
    if (n_sm == 0) {
        cudaDeviceGetAttribute(&n_sm, cudaDevAttrMultiProcessorCount, 0);
        if (n_sm <= 0) n_sm = 148;
        cudaFuncSetAttribute(w8a8_gemm_kernel,
                             cudaFuncAttributeMaxDynamicSharedMemorySize,
                             SMEM_TOTAL);
    }

    int grid = 2 * n_sm;
    if (grid > NTILES) grid = NTILES;

    // quantize pre-pass (16 floats/thread, MLP=4; also resets g_ctr)
    int nthx = MM * KK / 16;
    int nthw = NN * KK / 16;
    int nthtot = nthx + nthw;
    quantize_kernel<<<(nthtot + 255) / 256, 256>>>(
        (const float4*)x, (const float4*)w, xs, nthx, nthtot, grid);

    // persistent GEMM, 2 CTAs per SM, dynamic tiles
    w8a8_gemm_kernel<<<grid, NTHREADS, SMEM_TOTAL>>>(out, wsc, bias, xs);
}